// round 13
// baseline (speedup 1.0000x reference)
#include <cuda_runtime.h>

// LSTM_8615704395881: B=64, T=16384, I=1, H=32, O=1.  SINGLE fused kernel.
// 1 CTA/batch, 128 threads (4 homogeneous warps).
//   lane = 4*j_local + gate ; warp w owns hidden units [8w, 8w+8).
//   Per step: LDS h -> 32-MAC dot (f32x2, two 8-deep chains; x/bias seed
//   hoisted) -> MUFU.TANH act (0.5 folded into weights for sigmoid
//   gates) -> 3 shuffles (g,i,f; writer lane g==3 owns o) -> redundant
//   cell update -> h STS -> barrier; writer lane posts hres*W_lin[j] to
//   part[pb][k][j] in the wait window (replaces old fp16 scratch STG).
//   Once per 16 steps a distributed combine (4 steps/warp) reduces
//   part -> out[t] = x[t] + b_lin + sum_j. No scratch gmem, no 2nd kernel.

#define BATCH 64
#define TLEN  16384
#define HID   32
#define NT    128

typedef unsigned long long ull;
typedef unsigned int uint;

__device__ __forceinline__ float tanh_fast(float x) {
    float r; asm("tanh.approx.f32 %0, %1;" : "=f"(r) : "f"(x)); return r;
}
__device__ __forceinline__ ull fma2(ull a, ull b, ull c) {
    ull d; asm("fma.rn.f32x2 %0, %1, %2, %3;" : "=l"(d) : "l"(a), "l"(b), "l"(c));
    return d;
}
__device__ __forceinline__ ull add2(ull a, ull b) {
    ull d; asm("add.rn.f32x2 %0, %1, %2;" : "=l"(d) : "l"(a), "l"(b));
    return d;
}
__device__ __forceinline__ ull pack2(float x, float y) {
    ull v; asm("mov.b64 %0, {%1, %2};" : "=l"(v) : "f"(x), "f"(y)); return v;
}
__device__ __forceinline__ float2 unpack2(ull v) {
    float2 f; asm("mov.b64 {%0, %1}, %2;" : "=f"(f.x), "=f"(f.y) : "l"(v)); return f;
}

// one LSTM timestep; X0 = prepacked (x*wih + bias, 0) seed; PROW = SMEM row
// part[pb][k] receiving this step's per-unit head partial (writer lanes).
#define STEP(X0, HR, HW, PROW)                                                \
    do {                                                                      \
        ull a0 = (X0);                                                        \
        ull a1 = 0ull;                                                        \
        _Pragma("unroll")                                                     \
        for (int i = 0; i < 4; i++) {                                         \
            ulonglong2 ha  = *(const ulonglong2*)((HR) + 8 * i);              \
            ulonglong2 hb2 = *(const ulonglong2*)((HR) + 8 * i + 4);          \
            a0 = fma2(w2[4 * i + 0], ha.x,  a0);                              \
            a1 = fma2(w2[4 * i + 1], ha.y,  a1);                              \
            a0 = fma2(w2[4 * i + 2], hb2.x, a0);                              \
            a1 = fma2(w2[4 * i + 3], hb2.y, a1);                              \
        }                                                                     \
        float2 sf = unpack2(add2(a0, a1));                                    \
        float act = fmaf(tanh_fast(sf.x + sf.y), sa, sb);                     \
        float gv = __shfl_sync(0xffffffffu, act, base4 + 2);                  \
        float iv = __shfl_sync(0xffffffffu, act, base4);                      \
        float fv = __shfl_sync(0xffffffffu, act, base4 + 1);                  \
        c = fmaf(fv, c, iv * gv);                                             \
        float hres = act * tanh_fast(c);   /* act == o on writer lane */      \
        if (writer) (HW)[j] = hres;                                           \
        __syncthreads();                                                      \
        if (writer) (PROW)[j] = hres * wl;   /* in BAR wait window */         \
    } while (0)

// 16-step half-block: PB = part buffer, first step reads HRS.
#define HALF16(PB, HRS, XA, XB, XC, XD)                                       \
    do {                                                                      \
        ull s0  = pack2(fmaf((XA).x, wih, bsum), 0.f);                        \
        ull s1  = pack2(fmaf((XA).y, wih, bsum), 0.f);                        \
        ull s2  = pack2(fmaf((XA).z, wih, bsum), 0.f);                        \
        ull s3  = pack2(fmaf((XA).w, wih, bsum), 0.f);                        \
        ull s4  = pack2(fmaf((XB).x, wih, bsum), 0.f);                        \
        ull s5  = pack2(fmaf((XB).y, wih, bsum), 0.f);                        \
        ull s6  = pack2(fmaf((XB).z, wih, bsum), 0.f);                        \
        ull s7  = pack2(fmaf((XB).w, wih, bsum), 0.f);                        \
        ull s8  = pack2(fmaf((XC).x, wih, bsum), 0.f);                        \
        ull s9  = pack2(fmaf((XC).y, wih, bsum), 0.f);                        \
        ull s10 = pack2(fmaf((XC).z, wih, bsum), 0.f);                        \
        ull s11 = pack2(fmaf((XC).w, wih, bsum), 0.f);                        \
        ull s12 = pack2(fmaf((XD).x, wih, bsum), 0.f);                        \
        ull s13 = pack2(fmaf((XD).y, wih, bsum), 0.f);                        \
        ull s14 = pack2(fmaf((XD).z, wih, bsum), 0.f);                        \
        ull s15 = pack2(fmaf((XD).w, wih, bsum), 0.f);                        \
        STEP(s0,  (HRS), hb[1], (PB)[0]);                                     \
        STEP(s1,  hb[1], hb[0], (PB)[1]);                                     \
        STEP(s2,  hb[0], hb[1], (PB)[2]);                                     \
        STEP(s3,  hb[1], hb[0], (PB)[3]);                                     \
        STEP(s4,  hb[0], hb[1], (PB)[4]);                                     \
        STEP(s5,  hb[1], hb[0], (PB)[5]);                                     \
        STEP(s6,  hb[0], hb[1], (PB)[6]);                                     \
        STEP(s7,  hb[1], hb[0], (PB)[7]);                                     \
        STEP(s8,  hb[0], hb[1], (PB)[8]);                                     \
        STEP(s9,  hb[1], hb[0], (PB)[9]);                                     \
        STEP(s10, hb[0], hb[1], (PB)[10]);                                    \
        STEP(s11, hb[1], hb[0], (PB)[11]);                                    \
        STEP(s12, hb[0], hb[1], (PB)[12]);                                    \
        STEP(s13, hb[1], hb[0], (PB)[13]);                                    \
        STEP(s14, hb[0], hb[1], (PB)[14]);                                    \
        STEP(s15, hb[1], hb[0], (PB)[15]);                                    \
    } while (0)

// distributed combine of one 16-step block: warp w reduces steps 4w..4w+3.
// Lane l: step sk = 4w + (l>>3), reads 4 of 32 partials, octet shfl-reduce.
// XC = this thread's prefetched x[T0 + sk].
#define COMBINE(PB, T0, XC)                                                   \
    do {                                                                      \
        float4 v = *(const float4*)&(PB)[sk][(lane & 7) << 2];                \
        float s = (v.x + v.y) + (v.z + v.w);                                  \
        s += __shfl_xor_sync(0xffffffffu, s, 1);                              \
        s += __shfl_xor_sync(0xffffffffu, s, 2);                              \
        s += __shfl_xor_sync(0xffffffffu, s, 4);                              \
        if ((lane & 7) == 0) ob[(T0) + sk] = (XC) + bl + s;                   \
    } while (0)

__global__ __launch_bounds__(NT, 1)
void lstm_fused(const float* __restrict__ x,
                const float* __restrict__ W_ih,
                const float* __restrict__ W_hh,
                const float* __restrict__ b_ih,
                const float* __restrict__ b_hh,
                const float* __restrict__ W_lin,
                const float* __restrict__ b_lin,
                float* __restrict__ out)
{
    __shared__ __align__(128) float hb[2][HID];
    __shared__ __align__(16)  float part[2][16][HID];   // head partials

    const int tid  = threadIdx.x;
    const int wid  = tid >> 5;
    const int lane = tid & 31;
    const int b    = blockIdx.x;

    const int g   = lane & 3;                  // gate: 0=i 1=f 2=g 3=o
    const int j   = (wid << 3) + (lane >> 2);  // hidden unit
    const int row = (g << 5) + j;

    // sigmoid(z) = 0.5*tanh(z/2)+0.5 : fold the /2 into the weights
    const float scale = (g == 2) ? 1.0f : 0.5f;
    const float sa    = (g == 2) ? 1.0f : 0.5f;
    const float sb    = (g == 2) ? 0.0f : 0.5f;

    ull w2[16];
    #pragma unroll
    for (int k = 0; k < 16; k++) {
        float wa = W_hh[row * HID + 2 * k]     * scale;
        float wb = W_hh[row * HID + 2 * k + 1] * scale;
        w2[k] = pack2(wa, wb);
    }
    const float wih  = W_ih[row] * scale;
    const float bsum = (b_ih[row] + b_hh[row]) * scale;
    const int base4  = lane & ~3;
    const bool writer = (g == 3);              // owns o -> no o-shuffle
    const float wl   = writer ? W_lin[j] : 0.f;
    const float bl   = b_lin[0];
    const int sk     = (wid << 2) + (lane >> 3);   // combine step 0..15

    const float* xb = x   + (size_t)b * TLEN;
    float*       ob = out + (size_t)b * TLEN;
    float c = 0.f;

    if (tid < HID) hb[0][tid] = 0.f;
    __syncthreads();

    // x for steps t..t+15 in c-regs
    float4 c0 = __ldg((const float4*)(xb + 0));
    float4 c1 = __ldg((const float4*)(xb + 4));
    float4 c2 = __ldg((const float4*)(xb + 8));
    float4 c3 = __ldg((const float4*)(xb + 12));
    float xcB = 0.f;                           // combine-x, loop-carried

    for (int t = 0; t < TLEN; t += 32) {
        float xcA = __ldg(xb + t + sk);        // for COMBINE(part0, t)
        // prefetch x for steps t+16..t+31
        float4 n0 = __ldg((const float4*)(xb + t + 16));
        float4 n1 = __ldg((const float4*)(xb + t + 20));
        float4 n2 = __ldg((const float4*)(xb + t + 24));
        float4 n3 = __ldg((const float4*)(xb + t + 28));

        HALF16(part[0], hb[0], c0, c1, c2, c3);    // steps t..t+15

        if (t) COMBINE(part[1], t - 16, xcB);      // previous odd block

        // prefetch x for steps t+32..t+47 (wrap-masked on the last block)
        const int tn = (t + 32) & (TLEN - 1);
        c0 = __ldg((const float4*)(xb + tn));
        c1 = __ldg((const float4*)(xb + tn + 4));
        c2 = __ldg((const float4*)(xb + tn + 8));
        c3 = __ldg((const float4*)(xb + tn + 12));
        xcB = __ldg(xb + t + 16 + sk);             // for next COMBINE(part1)

        HALF16(part[1], hb[0], n0, n1, n2, n3);    // steps t+16..t+31

        COMBINE(part[0], t, xcA);                  // current even block
    }
    __syncthreads();                               // order final part1 STS
    COMBINE(part[1], TLEN - 16, xcB);              // last block
}

extern "C" void kernel_launch(void* const* d_in, const int* in_sizes, int n_in,
                              void* d_out, int out_size) {
    lstm_fused<<<BATCH, NT>>>(
        (const float*)d_in[0],   // x
        (const float*)d_in[1],   // W_ih
        (const float*)d_in[2],   // W_hh
        (const float*)d_in[3],   // b_ih
        (const float*)d_in[4],   // b_hh
        (const float*)d_in[5],   // W_lin
        (const float*)d_in[6],   // b_lin
        (float*)d_out);
}

// round 14
// speedup vs baseline: 1.0398x; 1.0398x over previous
#include <cuda_runtime.h>
#include <cuda_fp16.h>

// LSTM_8615704395881: B=64, T=16384, I=1, H=32, O=1.
// Kernel 1 (recurrent): 1 CTA/batch, 128 threads (4 homogeneous warps).
//   lane = 4*j_local + gate ; warp w owns hidden units [8w, 8w+8).
//   Per step: LDS h -> 32-MAC dot (f32x2, TWO 8-deep chains; x/bias seed
//   hoisted to block top) -> MUFU.TANH act (0.5 folded into weights for
//   sigmoid gates) -> 3 shuffles (g,i,f; writer lane g==3 owns o) ->
//   redundant cell update -> h STS (writer) -> barrier; plain fp16 STG
//   with static offsets in the wait window. 16-step unroll, wrap-masked
//   x prefetch.  [R9/R11 byte-identical — measured floor ~215 cyc/step]
// Kernel 2 (head): out = x + h_dev @ W_lin + b_lin. 2 rows/thread,
//   8 independent LDG.128 in flight. [R10 variant — best measured]

#define BATCH 64
#define TLEN  16384
#define HID   32
#define NT    128

typedef unsigned long long ull;
typedef unsigned int uint;

__device__ __align__(16) __half h_dev[(size_t)BATCH * TLEN * HID];  // 64 MB fp16 scratch

__device__ __forceinline__ float tanh_fast(float x) {
    float r; asm("tanh.approx.f32 %0, %1;" : "=f"(r) : "f"(x)); return r;
}
__device__ __forceinline__ ull fma2(ull a, ull b, ull c) {
    ull d; asm("fma.rn.f32x2 %0, %1, %2, %3;" : "=l"(d) : "l"(a), "l"(b), "l"(c));
    return d;
}
__device__ __forceinline__ ull add2(ull a, ull b) {
    ull d; asm("add.rn.f32x2 %0, %1, %2;" : "=l"(d) : "l"(a), "l"(b));
    return d;
}
__device__ __forceinline__ ull pack2(float x, float y) {
    ull v; asm("mov.b64 %0, {%1, %2};" : "=l"(v) : "f"(x), "f"(y)); return v;
}
__device__ __forceinline__ float2 unpack2(ull v) {
    float2 f; asm("mov.b64 {%0, %1}, %2;" : "=f"(f.x), "=f"(f.y) : "l"(v)); return f;
}

// one LSTM timestep; X0 = prepacked (x*wih + bias, 0) seed; SOFF = static
// element offset into the h scratch for this step within the 16-block.
#define STEP(X0, HR, HW, SOFF)                                                \
    do {                                                                      \
        ull a0 = (X0);                                                        \
        ull a1 = 0ull;                                                        \
        _Pragma("unroll")                                                     \
        for (int i = 0; i < 4; i++) {                                         \
            ulonglong2 ha  = *(const ulonglong2*)((HR) + 8 * i);              \
            ulonglong2 hb2 = *(const ulonglong2*)((HR) + 8 * i + 4);          \
            a0 = fma2(w2[4 * i + 0], ha.x,  a0);                              \
            a1 = fma2(w2[4 * i + 1], ha.y,  a1);                              \
            a0 = fma2(w2[4 * i + 2], hb2.x, a0);                              \
            a1 = fma2(w2[4 * i + 3], hb2.y, a1);                              \
        }                                                                     \
        float2 sf = unpack2(add2(a0, a1));                                    \
        float act = fmaf(tanh_fast(sf.x + sf.y), sa, sb);                     \
        float gv = __shfl_sync(0xffffffffu, act, base4 + 2);                  \
        float iv = __shfl_sync(0xffffffffu, act, base4);                      \
        float fv = __shfl_sync(0xffffffffu, act, base4 + 1);                  \
        c = fmaf(fv, c, iv * gv);                                             \
        float hres = act * tanh_fast(c);   /* act == o on writer lane */      \
        if (writer) (HW)[j] = hres;                                           \
        __syncthreads();                                                      \
        if (writer) gout[SOFF] = __float2half_rn(hres); /* in wait window */  \
    } while (0)

__global__ __launch_bounds__(NT, 1)
void lstm_rec(const float* __restrict__ x,
              const float* __restrict__ W_ih,
              const float* __restrict__ W_hh,
              const float* __restrict__ b_ih,
              const float* __restrict__ b_hh)
{
    __shared__ __align__(128) float hb[2][HID];

    const int tid  = threadIdx.x;
    const int wid  = tid >> 5;
    const int lane = tid & 31;
    const int b    = blockIdx.x;

    const int g   = lane & 3;                  // gate: 0=i 1=f 2=g 3=o
    const int j   = (wid << 3) + (lane >> 2);  // hidden unit
    const int row = (g << 5) + j;

    // sigmoid(z) = 0.5*tanh(z/2)+0.5 : fold the /2 into the weights
    const float scale = (g == 2) ? 1.0f : 0.5f;
    const float sa    = (g == 2) ? 1.0f : 0.5f;
    const float sb    = (g == 2) ? 0.0f : 0.5f;

    ull w2[16];
    #pragma unroll
    for (int k = 0; k < 16; k++) {
        float wa = W_hh[row * HID + 2 * k]     * scale;
        float wb = W_hh[row * HID + 2 * k + 1] * scale;
        w2[k] = pack2(wa, wb);
    }
    const float wih  = W_ih[row] * scale;
    const float bsum = (b_ih[row] + b_hh[row]) * scale;
    const int base4  = lane & ~3;
    const bool writer = (g == 3);              // owns o -> no o-shuffle

    __half* gout = h_dev + (size_t)b * TLEN * HID + j;
    const float* xb = x + (size_t)b * TLEN;
    float c = 0.f;

    if (tid < HID) hb[0][tid] = 0.f;
    __syncthreads();

    // prefetch one 16-step block ahead (wrap-masked, no compare/select)
    float4 xn0 = __ldg((const float4*)xb);
    float4 xn1 = __ldg((const float4*)(xb + 4));
    float4 xn2 = __ldg((const float4*)(xb + 8));
    float4 xn3 = __ldg((const float4*)(xb + 12));
    for (int t = 0; t < TLEN; t += 16) {
        const float4 xa = xn0, xbq = xn1, xcq = xn2, xdq = xn3;
        const int tn = (t + 16) & (TLEN - 1);
        xn0 = __ldg((const float4*)(xb + tn));
        xn1 = __ldg((const float4*)(xb + tn + 4));
        xn2 = __ldg((const float4*)(xb + tn + 8));
        xn3 = __ldg((const float4*)(xb + tn + 12));

        // hoist all x/bias seeds off the per-step critical path
        ull s0  = pack2(fmaf(xa.x,  wih, bsum), 0.f);
        ull s1  = pack2(fmaf(xa.y,  wih, bsum), 0.f);
        ull s2  = pack2(fmaf(xa.z,  wih, bsum), 0.f);
        ull s3  = pack2(fmaf(xa.w,  wih, bsum), 0.f);
        ull s4  = pack2(fmaf(xbq.x, wih, bsum), 0.f);
        ull s5  = pack2(fmaf(xbq.y, wih, bsum), 0.f);
        ull s6  = pack2(fmaf(xbq.z, wih, bsum), 0.f);
        ull s7  = pack2(fmaf(xbq.w, wih, bsum), 0.f);
        ull s8  = pack2(fmaf(xcq.x, wih, bsum), 0.f);
        ull s9  = pack2(fmaf(xcq.y, wih, bsum), 0.f);
        ull s10 = pack2(fmaf(xcq.z, wih, bsum), 0.f);
        ull s11 = pack2(fmaf(xcq.w, wih, bsum), 0.f);
        ull s12 = pack2(fmaf(xdq.x, wih, bsum), 0.f);
        ull s13 = pack2(fmaf(xdq.y, wih, bsum), 0.f);
        ull s14 = pack2(fmaf(xdq.z, wih, bsum), 0.f);
        ull s15 = pack2(fmaf(xdq.w, wih, bsum), 0.f);

        STEP(s0,  hb[0], hb[1],  0 * HID);
        STEP(s1,  hb[1], hb[0],  1 * HID);
        STEP(s2,  hb[0], hb[1],  2 * HID);
        STEP(s3,  hb[1], hb[0],  3 * HID);
        STEP(s4,  hb[0], hb[1],  4 * HID);
        STEP(s5,  hb[1], hb[0],  5 * HID);
        STEP(s6,  hb[0], hb[1],  6 * HID);
        STEP(s7,  hb[1], hb[0],  7 * HID);
        STEP(s8,  hb[0], hb[1],  8 * HID);
        STEP(s9,  hb[1], hb[0],  9 * HID);
        STEP(s10, hb[0], hb[1], 10 * HID);
        STEP(s11, hb[1], hb[0], 11 * HID);
        STEP(s12, hb[0], hb[1], 12 * HID);
        STEP(s13, hb[1], hb[0], 13 * HID);
        STEP(s14, hb[0], hb[1], 14 * HID);
        STEP(s15, hb[1], hb[0], 15 * HID);
        gout += 16 * HID;                      // one bump per block
    }
}

// 2 rows per thread, direct (coalesced) loads, 8 independent LDG.128 in
// flight per thread. Row pair is (base+tid, base+256+tid) so both the
// h_dev reads and the x/out accesses stay fully coalesced per warp.
__global__ __launch_bounds__(256, 4)
void lin_head(const float* __restrict__ x,
              const float* __restrict__ W_lin,
              const float* __restrict__ b_lin,
              float* __restrict__ out)
{
    const int tid = threadIdx.x;
    const size_t r0 = (size_t)blockIdx.x * 512 + tid;    // row 0
    const size_t r1 = r0 + 256;                          // row 1

    const uint4* h0p = (const uint4*)(h_dev + r0 * HID);
    const uint4* h1p = (const uint4*)(h_dev + r1 * HID);

    // issue all 8 row loads + 2 x loads up front (max MLP)
    uint4 u0 = h0p[0], u1 = h0p[1], u2 = h0p[2], u3 = h0p[3];
    uint4 v0 = h1p[0], v1 = h1p[1], v2 = h1p[2], v3 = h1p[3];
    float x0 = x[r0], x1 = x[r1];

    float w[32];
    #pragma unroll
    for (int k = 0; k < 8; k++) {
        float4 wv = __ldg((const float4*)W_lin + k);
        w[4*k] = wv.x; w[4*k+1] = wv.y; w[4*k+2] = wv.z; w[4*k+3] = wv.w;
    }
    const float bl = __ldg(b_lin);

    #define ROWACC(ACC, Q, WOFF)                                              \
        do {                                                                  \
            float2 f0 = __half22float2(*(const __half2*)&(Q).x);              \
            float2 f1 = __half22float2(*(const __half2*)&(Q).y);              \
            float2 f2 = __half22float2(*(const __half2*)&(Q).z);              \
            float2 f3 = __half22float2(*(const __half2*)&(Q).w);              \
            ACC = fmaf(f0.x, w[(WOFF)+0], fmaf(f0.y, w[(WOFF)+1], ACC));      \
            ACC = fmaf(f1.x, w[(WOFF)+2], fmaf(f1.y, w[(WOFF)+3], ACC));      \
            ACC = fmaf(f2.x, w[(WOFF)+4], fmaf(f2.y, w[(WOFF)+5], ACC));      \
            ACC = fmaf(f3.x, w[(WOFF)+6], fmaf(f3.y, w[(WOFF)+7], ACC));      \
        } while (0)

    float a0 = 0.f, a1 = 0.f;
    ROWACC(a0, u0,  0); ROWACC(a0, u1,  8); ROWACC(a0, u2, 16); ROWACC(a0, u3, 24);
    ROWACC(a1, v0,  0); ROWACC(a1, v1,  8); ROWACC(a1, v2, 16); ROWACC(a1, v3, 24);
    #undef ROWACC

    out[r0] = x0 + bl + a0;
    out[r1] = x1 + bl + a1;
}

extern "C" void kernel_launch(void* const* d_in, const int* in_sizes, int n_in,
                              void* d_out, int out_size) {
    lstm_rec<<<BATCH, NT>>>(
        (const float*)d_in[0],   // x
        (const float*)d_in[1],   // W_ih
        (const float*)d_in[2],   // W_hh
        (const float*)d_in[3],   // b_ih
        (const float*)d_in[4]);  // b_hh
    lin_head<<<(BATCH * TLEN) / 512, 256>>>(
        (const float*)d_in[0],   // x
        (const float*)d_in[5],   // W_lin
        (const float*)d_in[6],   // b_lin
        (float*)d_out);
}

// round 15
// speedup vs baseline: 1.0510x; 1.0107x over previous
#include <cuda_runtime.h>
#include <cuda_fp16.h>

// LSTM_8615704395881: B=64, T=16384, I=1, H=32, O=1.
// FINAL (R11 configuration — best measured: 1885.8 us).
// Kernel 1 (recurrent): 1 CTA/batch, 128 threads (4 homogeneous warps).
//   lane = 4*j_local + gate ; warp w owns hidden units [8w, 8w+8).
//   Per step: LDS h -> 32-MAC dot (f32x2, two 8-deep chains; x/bias seed
//   hoisted) -> MUFU.TANH act (0.5 folded into weights for sigmoid
//   gates) -> 3 shuffles (g,i,f; writer lane g==3 owns o) -> redundant
//   cell update -> h STS (writer) -> barrier; plain fp16 STG with static
//   offsets in the wait window. 16-step unroll, wrap-masked x prefetch.
//   Measured structural floor ~215 cyc/step.
// Kernel 2 (head): out = x + h_dev @ W_lin + b_lin. 4 rows/thread,
//   16 independent LDG.128 in flight, no SMEM.

#define BATCH 64
#define TLEN  16384
#define HID   32
#define NT    128

typedef unsigned long long ull;
typedef unsigned int uint;

__device__ __align__(16) __half h_dev[(size_t)BATCH * TLEN * HID];  // 64 MB fp16 scratch

__device__ __forceinline__ float tanh_fast(float x) {
    float r; asm("tanh.approx.f32 %0, %1;" : "=f"(r) : "f"(x)); return r;
}
__device__ __forceinline__ ull fma2(ull a, ull b, ull c) {
    ull d; asm("fma.rn.f32x2 %0, %1, %2, %3;" : "=l"(d) : "l"(a), "l"(b), "l"(c));
    return d;
}
__device__ __forceinline__ ull add2(ull a, ull b) {
    ull d; asm("add.rn.f32x2 %0, %1, %2;" : "=l"(d) : "l"(a), "l"(b));
    return d;
}
__device__ __forceinline__ ull pack2(float x, float y) {
    ull v; asm("mov.b64 %0, {%1, %2};" : "=l"(v) : "f"(x), "f"(y)); return v;
}
__device__ __forceinline__ float2 unpack2(ull v) {
    float2 f; asm("mov.b64 {%0, %1}, %2;" : "=f"(f.x), "=f"(f.y) : "l"(v)); return f;
}

// one LSTM timestep; X0 = prepacked (x*wih + bias, 0) seed; SOFF = static
// element offset into the h scratch for this step within the 16-block.
#define STEP(X0, HR, HW, SOFF)                                                \
    do {                                                                      \
        ull a0 = (X0);                                                        \
        ull a1 = 0ull;                                                        \
        _Pragma("unroll")                                                     \
        for (int i = 0; i < 4; i++) {                                         \
            ulonglong2 ha  = *(const ulonglong2*)((HR) + 8 * i);              \
            ulonglong2 hb2 = *(const ulonglong2*)((HR) + 8 * i + 4);          \
            a0 = fma2(w2[4 * i + 0], ha.x,  a0);                              \
            a1 = fma2(w2[4 * i + 1], ha.y,  a1);                              \
            a0 = fma2(w2[4 * i + 2], hb2.x, a0);                              \
            a1 = fma2(w2[4 * i + 3], hb2.y, a1);                              \
        }                                                                     \
        float2 sf = unpack2(add2(a0, a1));                                    \
        float act = fmaf(tanh_fast(sf.x + sf.y), sa, sb);                     \
        float gv = __shfl_sync(0xffffffffu, act, base4 + 2);                  \
        float iv = __shfl_sync(0xffffffffu, act, base4);                      \
        float fv = __shfl_sync(0xffffffffu, act, base4 + 1);                  \
        c = fmaf(fv, c, iv * gv);                                             \
        float hres = act * tanh_fast(c);   /* act == o on writer lane */      \
        if (writer) (HW)[j] = hres;                                           \
        __syncthreads();                                                      \
        if (writer) gout[SOFF] = __float2half_rn(hres); /* in wait window */  \
    } while (0)

__global__ __launch_bounds__(NT, 1)
void lstm_rec(const float* __restrict__ x,
              const float* __restrict__ W_ih,
              const float* __restrict__ W_hh,
              const float* __restrict__ b_ih,
              const float* __restrict__ b_hh)
{
    __shared__ __align__(128) float hb[2][HID];

    const int tid  = threadIdx.x;
    const int wid  = tid >> 5;
    const int lane = tid & 31;
    const int b    = blockIdx.x;

    const int g   = lane & 3;                  // gate: 0=i 1=f 2=g 3=o
    const int j   = (wid << 3) + (lane >> 2);  // hidden unit
    const int row = (g << 5) + j;

    // sigmoid(z) = 0.5*tanh(z/2)+0.5 : fold the /2 into the weights
    const float scale = (g == 2) ? 1.0f : 0.5f;
    const float sa    = (g == 2) ? 1.0f : 0.5f;
    const float sb    = (g == 2) ? 0.0f : 0.5f;

    ull w2[16];
    #pragma unroll
    for (int k = 0; k < 16; k++) {
        float wa = W_hh[row * HID + 2 * k]     * scale;
        float wb = W_hh[row * HID + 2 * k + 1] * scale;
        w2[k] = pack2(wa, wb);
    }
    const float wih  = W_ih[row] * scale;
    const float bsum = (b_ih[row] + b_hh[row]) * scale;
    const int base4  = lane & ~3;
    const bool writer = (g == 3);              // owns o -> no o-shuffle

    __half* gout = h_dev + (size_t)b * TLEN * HID + j;
    const float* xb = x + (size_t)b * TLEN;
    float c = 0.f;

    if (tid < HID) hb[0][tid] = 0.f;
    __syncthreads();

    // prefetch one 16-step block ahead (wrap-masked, no compare/select)
    float4 xn0 = __ldg((const float4*)xb);
    float4 xn1 = __ldg((const float4*)(xb + 4));
    float4 xn2 = __ldg((const float4*)(xb + 8));
    float4 xn3 = __ldg((const float4*)(xb + 12));
    for (int t = 0; t < TLEN; t += 16) {
        const float4 xa = xn0, xbq = xn1, xcq = xn2, xdq = xn3;
        const int tn = (t + 16) & (TLEN - 1);
        xn0 = __ldg((const float4*)(xb + tn));
        xn1 = __ldg((const float4*)(xb + tn + 4));
        xn2 = __ldg((const float4*)(xb + tn + 8));
        xn3 = __ldg((const float4*)(xb + tn + 12));

        // hoist all x/bias seeds off the per-step critical path
        ull s0  = pack2(fmaf(xa.x,  wih, bsum), 0.f);
        ull s1  = pack2(fmaf(xa.y,  wih, bsum), 0.f);
        ull s2  = pack2(fmaf(xa.z,  wih, bsum), 0.f);
        ull s3  = pack2(fmaf(xa.w,  wih, bsum), 0.f);
        ull s4  = pack2(fmaf(xbq.x, wih, bsum), 0.f);
        ull s5  = pack2(fmaf(xbq.y, wih, bsum), 0.f);
        ull s6  = pack2(fmaf(xbq.z, wih, bsum), 0.f);
        ull s7  = pack2(fmaf(xbq.w, wih, bsum), 0.f);
        ull s8  = pack2(fmaf(xcq.x, wih, bsum), 0.f);
        ull s9  = pack2(fmaf(xcq.y, wih, bsum), 0.f);
        ull s10 = pack2(fmaf(xcq.z, wih, bsum), 0.f);
        ull s11 = pack2(fmaf(xcq.w, wih, bsum), 0.f);
        ull s12 = pack2(fmaf(xdq.x, wih, bsum), 0.f);
        ull s13 = pack2(fmaf(xdq.y, wih, bsum), 0.f);
        ull s14 = pack2(fmaf(xdq.z, wih, bsum), 0.f);
        ull s15 = pack2(fmaf(xdq.w, wih, bsum), 0.f);

        STEP(s0,  hb[0], hb[1],  0 * HID);
        STEP(s1,  hb[1], hb[0],  1 * HID);
        STEP(s2,  hb[0], hb[1],  2 * HID);
        STEP(s3,  hb[1], hb[0],  3 * HID);
        STEP(s4,  hb[0], hb[1],  4 * HID);
        STEP(s5,  hb[1], hb[0],  5 * HID);
        STEP(s6,  hb[0], hb[1],  6 * HID);
        STEP(s7,  hb[1], hb[0],  7 * HID);
        STEP(s8,  hb[0], hb[1],  8 * HID);
        STEP(s9,  hb[1], hb[0],  9 * HID);
        STEP(s10, hb[0], hb[1], 10 * HID);
        STEP(s11, hb[1], hb[0], 11 * HID);
        STEP(s12, hb[0], hb[1], 12 * HID);
        STEP(s13, hb[1], hb[0], 13 * HID);
        STEP(s14, hb[0], hb[1], 14 * HID);
        STEP(s15, hb[1], hb[0], 15 * HID);
        gout += 16 * HID;                      // one bump per block
    }
}

// 4 rows per thread: 16 independent LDG.128 (h) + 4 LDG.32 (x) issued up
// front, then consumed in load order. Rows r, r+256, r+512, r+768 keep
// every access fully coalesced per warp.
__global__ __launch_bounds__(256)
void lin_head(const float* __restrict__ x,
              const float* __restrict__ W_lin,
              const float* __restrict__ b_lin,
              float* __restrict__ out)
{
    const int tid = threadIdx.x;
    const size_t r0 = (size_t)blockIdx.x * 1024 + tid;
    const size_t r1 = r0 + 256;
    const size_t r2 = r0 + 512;
    const size_t r3 = r0 + 768;

    const uint4* h0p = (const uint4*)(h_dev + r0 * HID);
    const uint4* h1p = (const uint4*)(h_dev + r1 * HID);
    const uint4* h2p = (const uint4*)(h_dev + r2 * HID);
    const uint4* h3p = (const uint4*)(h_dev + r3 * HID);

    // issue all loads up front (max MLP)
    uint4 u0 = h0p[0], u1 = h0p[1], u2 = h0p[2], u3 = h0p[3];
    uint4 v0 = h1p[0], v1 = h1p[1], v2 = h1p[2], v3 = h1p[3];
    uint4 p0 = h2p[0], p1 = h2p[1], p2 = h2p[2], p3 = h2p[3];
    uint4 q0 = h3p[0], q1 = h3p[1], q2 = h3p[2], q3 = h3p[3];
    float x0 = x[r0], x1 = x[r1], x2 = x[r2], x3 = x[r3];

    float w[32];
    #pragma unroll
    for (int k = 0; k < 8; k++) {
        float4 wv = __ldg((const float4*)W_lin + k);
        w[4*k] = wv.x; w[4*k+1] = wv.y; w[4*k+2] = wv.z; w[4*k+3] = wv.w;
    }
    const float bl = __ldg(b_lin);

    #define ROWACC(ACC, Q, WOFF)                                              \
        do {                                                                  \
            float2 f0 = __half22float2(*(const __half2*)&(Q).x);              \
            float2 f1 = __half22float2(*(const __half2*)&(Q).y);              \
            float2 f2 = __half22float2(*(const __half2*)&(Q).z);              \
            float2 f3 = __half22float2(*(const __half2*)&(Q).w);              \
            ACC = fmaf(f0.x, w[(WOFF)+0], fmaf(f0.y, w[(WOFF)+1], ACC));      \
            ACC = fmaf(f1.x, w[(WOFF)+2], fmaf(f1.y, w[(WOFF)+3], ACC));      \
            ACC = fmaf(f2.x, w[(WOFF)+4], fmaf(f2.y, w[(WOFF)+5], ACC));      \
            ACC = fmaf(f3.x, w[(WOFF)+6], fmaf(f3.y, w[(WOFF)+7], ACC));      \
        } while (0)

    float a0 = 0.f, a1 = 0.f, a2 = 0.f, a3 = 0.f;
    ROWACC(a0, u0,  0); ROWACC(a0, u1,  8); ROWACC(a0, u2, 16); ROWACC(a0, u3, 24);
    out[r0] = x0 + bl + a0;
    ROWACC(a1, v0,  0); ROWACC(a1, v1,  8); ROWACC(a1, v2, 16); ROWACC(a1, v3, 24);
    out[r1] = x1 + bl + a1;
    ROWACC(a2, p0,  0); ROWACC(a2, p1,  8); ROWACC(a2, p2, 16); ROWACC(a2, p3, 24);
    out[r2] = x2 + bl + a2;
    ROWACC(a3, q0,  0); ROWACC(a3, q1,  8); ROWACC(a3, q2, 16); ROWACC(a3, q3, 24);
    out[r3] = x3 + bl + a3;
    #undef ROWACC
}

extern "C" void kernel_launch(void* const* d_in, const int* in_sizes, int n_in,
                              void* d_out, int out_size) {
    lstm_rec<<<BATCH, NT>>>(
        (const float*)d_in[0],   // x
        (const float*)d_in[1],   // W_ih
        (const float*)d_in[2],   // W_hh
        (const float*)d_in[3],   // b_ih
        (const float*)d_in[4]);  // b_hh
    lin_head<<<(BATCH * TLEN) / 1024, 256>>>(
        (const float*)d_in[0],   // x
        (const float*)d_in[5],   // W_lin
        (const float*)d_in[6],   // b_lin
        (float*)d_out);
}